// round 16
// baseline (speedup 1.0000x reference)
#include <cuda_runtime.h>
#include <math.h>
#include <stdint.h>

#define N_LEVELS 16
#define N_POINTS 524288
#define HASH_MASK 0x7FFFFu       // hashed level size = 2^19 exactly
#define P1 2654435761u
#define P2 805459861u

#define NBUCK 32768              // 32^3 Morton buckets (~16 pts/bucket)
#define SCAN_BLOCKS 32           // 32 blocks x 1024 elems

// Static scratch (no allocation allowed). __device__ globals are
// zero-initialized at load; scanA re-zeroes g_hist4 every launch, so no
// memset node is needed and graph replays are deterministic.
__device__ uint4    g_hist4[NBUCK / 4];   // counts; RETURNED TO ZERO by scanA
__device__ uint4    g_off4[NBUCK / 4];    // exclusive offsets within scan-block
__device__ unsigned g_btot[SCAN_BLOCKS];  // scan-block totals -> exclusive
__device__ unsigned g_rank[N_POINTS];     // within-bucket rank (from histo)
__device__ float4   g_sorted[N_POINTS];   // (x,y,z, bitcast(orig index))

struct Scales { float s[N_LEVELS]; };

// ---------------- sort pipeline ----------------

__device__ __forceinline__ unsigned spread3(unsigned v) {
    v &= 0x3Fu;
    v = (v | (v << 16)) & 0x030000FFu;
    v = (v | (v << 8))  & 0x0300F00Fu;
    v = (v | (v << 4))  & 0x030C30C3u;
    v = (v | (v << 2))  & 0x09249249u;
    return v;
}

__device__ __forceinline__ unsigned bucket_of(float x, float y, float z) {
    unsigned cx = min((unsigned)(x * 32.0f), 31u);
    unsigned cy = min((unsigned)(y * 32.0f), 31u);
    unsigned cz = min((unsigned)(z * 32.0f), 31u);
    return spread3(cx) | (spread3(cy) << 1) | (spread3(cz) << 2);  // 15-bit Morton
}

// histo: count AND capture each point's within-bucket rank (the atomic's
// return value) so the scatter is atomic-free.
__global__ void k_histo(const float* __restrict__ inputs) {
    unsigned i = blockIdx.x * blockDim.x + threadIdx.x;
    float x = inputs[i * 3 + 0];
    float y = inputs[i * 3 + 1];
    float z = inputs[i * 3 + 2];
    unsigned b = bucket_of(x, y, z);
    unsigned* hist = reinterpret_cast<unsigned*>(g_hist4);
    g_rank[i] = atomicAdd(&hist[b], 1u);   // coalesced store
}

// scanA: 32 blocks x 256 threads; thread t owns ONE uint4 (warp = 512B
// contiguous -> fully coalesced). Also ZEROES g_hist4 for the next replay.
__global__ __launch_bounds__(256) void k_scanA() {
    __shared__ unsigned s[256];
    unsigned t = threadIdx.x;
    unsigned gi = blockIdx.x * 256u + t;

    uint4 v = g_hist4[gi];
    unsigned sum = v.x + v.y + v.z + v.w;

    s[t] = sum;
    __syncthreads();
    for (int d = 1; d < 256; d <<= 1) {
        unsigned add = (t >= (unsigned)d) ? s[t - d] : 0u;
        __syncthreads();
        s[t] += add;
        __syncthreads();
    }
    unsigned run = s[t] - sum;     // exclusive prefix of this chunk in block

    uint4 o;
    o.x = run;
    o.y = run + v.x;
    o.z = run + v.x + v.y;
    o.w = run + v.x + v.y + v.z;
    g_off4[gi]  = o;
    g_hist4[gi] = make_uint4(0u, 0u, 0u, 0u);   // ready for next launch

    if (t == 255u) g_btot[blockIdx.x] = s[255];
}

// scanB: one warp exclusive-scans the 32 block totals via shuffles.
__global__ void k_scanB() {
    unsigned t = threadIdx.x;           // 32 threads
    unsigned v = g_btot[t];
    unsigned x = v;
#pragma unroll
    for (int d = 1; d < 32; d <<= 1) {
        unsigned n = __shfl_up_sync(0xFFFFFFFFu, x, d);
        if (t >= (unsigned)d) x += n;
    }
    g_btot[t] = x - v;                  // exclusive
}

// Scatter: ATOMIC-FREE. slot = captured rank + bucket offset + block offset.
__global__ void k_scatter(const float* __restrict__ inputs) {
    unsigned i = blockIdx.x * blockDim.x + threadIdx.x;
    float x = inputs[i * 3 + 0];
    float y = inputs[i * 3 + 1];
    float z = inputs[i * 3 + 2];
    unsigned b = bucket_of(x, y, z);
    const unsigned* off = reinterpret_cast<const unsigned*>(g_off4);
    unsigned pos = g_rank[i] + __ldg(&off[b]) + __ldg(&g_btot[b >> 10]);
    g_sorted[pos] = make_float4(x, y, z, __uint_as_float(i));
}

// ---------------- main encode ----------------
// Gather/arithmetic identical to the proven R7 body. Warp-private SMEM row
// staging for the output: STS into padded rows (stride 36 floats = 144B,
// 16B-aligned for every lane -> no misaligned float4), then 8 instructions
// each write 4 COMPLETE 128B rows (4 wavefronts instead of 32).
// Bank math (bank = word_addr mod 32; 128-bit ops process 8 lanes/phase):
//   STS.128: lanes 0..7 -> banks (36L+c0) mod 32 = (4L+c0) mod 32, distinct.
//   LDS.128: phase has fixed row r, chunks c=0..7 -> banks 4(r+c) mod 32,
//            distinct. Both conflict-free.

__global__ __launch_bounds__(256) void hashenc_main(
    const float2* __restrict__ emb,
    const int*    __restrict__ offs,
    float2*       __restrict__ out,
    Scales sc)
{
    __shared__ float s_st[8][32 * 36];   // 8 warps x (32 rows x 36 floats) = 36KB

    const unsigned kRes[5] = {16u, 23u, 31u, 43u, 59u};

    unsigned tid  = threadIdx.x;
    unsigned w    = tid >> 5;
    unsigned lane = tid & 31u;
    unsigned i = blockIdx.x * 256u + tid;

    float4 pt = g_sorted[i];                       // 1 coalesced LDG.128
    float x = pt.x, y = pt.y, z = pt.z;
    unsigned p = __float_as_uint(pt.w);
    float* mys = s_st[w];

#pragma unroll
    for (int h = 0; h < 2; h++) {                  // two halves of 8 levels
        float acc[16];
#pragma unroll
        for (int l8 = 0; l8 < 8; l8++) {
            const int l = h * 8 + l8;
            float scale = sc.s[l];
            // plain fp32 multiply (bit-exact vs jnp inputs*scale)
            float px = x * scale, py = y * scale, pz = z * scale;
            float fx0 = floorf(px), fy0 = floorf(py), fz0 = floorf(pz);
            float fx = px - fx0, fy = py - fy0, fz = pz - fz0;
            unsigned gx = (unsigned)fx0, gy = (unsigned)fy0, gz = (unsigned)fz0;
            unsigned base = (unsigned)__ldg(&offs[l]);

            unsigned idx[8];
            if (l >= 5) {
                // hashed: (cx*1 ^ cy*P1 ^ cz*P2) & (2^19-1)
                unsigned hy0 = gy * P1, hy1 = hy0 + P1;
                unsigned hz0 = gz * P2, hz1 = hz0 + P2;
                unsigned s00 = hy0 ^ hz0, s10 = hy1 ^ hz0;
                unsigned s01 = hy0 ^ hz1, s11 = hy1 ^ hz1;
                unsigned x0 = gx, x1 = gx + 1u;
                idx[0] = (x0 ^ s00) & HASH_MASK;
                idx[1] = (x1 ^ s00) & HASH_MASK;
                idx[2] = (x0 ^ s10) & HASH_MASK;
                idx[3] = (x1 ^ s10) & HASH_MASK;
                idx[4] = (x0 ^ s01) & HASH_MASK;
                idx[5] = (x1 ^ s01) & HASH_MASK;
                idx[6] = (x0 ^ s11) & HASH_MASK;
                idx[7] = (x1 ^ s11) & HASH_MASK;
            } else {
                // dense: row-major within res^3, corners clamped to res-1
                unsigned res = kRes[l];
                unsigned rm1 = res - 1u;
                unsigned rr  = res * res;
                unsigned x0 = min(gx, rm1),       x1 = min(gx + 1u, rm1);
                unsigned y0 = min(gy, rm1) * res, y1 = min(gy + 1u, rm1) * res;
                unsigned z0 = min(gz, rm1) * rr,  z1 = min(gz + 1u, rm1) * rr;
                idx[0] = x0 + y0 + z0;
                idx[1] = x1 + y0 + z0;
                idx[2] = x0 + y1 + z0;
                idx[3] = x1 + y1 + z0;
                idx[4] = x0 + y0 + z1;
                idx[5] = x1 + y0 + z1;
                idx[6] = x0 + y1 + z1;
                idx[7] = x1 + y1 + z1;
            }

            float2 e[8];
#pragma unroll
            for (int c = 0; c < 8; c++)
                e[c] = __ldg(&emb[base + idx[c]]);

            float wx[2] = {1.0f - fx, fx};
            float wy[2] = {1.0f - fy, fy};
            float wz[2] = {1.0f - fz, fz};
            float ox = 0.0f, oy = 0.0f;
#pragma unroll
            for (int c = 0; c < 8; c++) {
                float wgt = wx[c & 1] * wy[(c >> 1) & 1] * wz[(c >> 2) & 1];
                ox += wgt * e[c].x;
                oy += wgt * e[c].y;
            }
            acc[l8 * 2 + 0] = ox;
            acc[l8 * 2 + 1] = oy;
        }
        // Stage this half into my padded SMEM row (aligned, conflict-free).
#pragma unroll
        for (int q = 0; q < 4; q++) {
            *(float4*)&mys[lane * 36u + (unsigned)(h * 4 + q) * 4u] =
                make_float4(acc[q * 4 + 0], acc[q * 4 + 1],
                            acc[q * 4 + 2], acc[q * 4 + 3]);
        }
    }

    __syncwarp();

    // Row-grouped writeback: instruction s writes rows 4s..4s+3 completely
    // (4 x 128B lines -> 4 wavefronts instead of 32).
#pragma unroll
    for (int s = 0; s < 8; s++) {
        unsigned r = (unsigned)s * 4u + (lane >> 3);
        unsigned c = lane & 7u;
        unsigned pr = __shfl_sync(0xFFFFFFFFu, p, (int)r);
        float4 v = *(float4*)&mys[r * 36u + c * 4u];
        __stcs((float4*)((float*)out + (size_t)pr * 32u) + c, v);
    }
}

// ---------------- launch ----------------

extern "C" void kernel_launch(void* const* d_in, const int* in_sizes, int n_in,
                              void* d_out, int out_size)
{
    const float*  inputs = (const float*)d_in[0];
    const float2* emb    = (const float2*)d_in[1];
    const int*    offs   = (const int*)d_in[2];
    float2*       out    = (float2*)d_out;

    // scale[l] = float32(16 * (2^(7/15))^l), computed in double so the float32
    // cast absorbs any sub-ulp libm difference vs numpy.
    Scales sc;
    double ratio = exp2(7.0 / 15.0);
    for (int l = 0; l < N_LEVELS; l++)
        sc.s[l] = (float)(16.0 * pow(ratio, (double)l));

    k_histo  <<<N_POINTS / 256, 256>>>(inputs);
    k_scanA  <<<SCAN_BLOCKS, 256>>>();
    k_scanB  <<<1, 32>>>();
    k_scatter<<<N_POINTS / 256, 256>>>(inputs);
    hashenc_main<<<N_POINTS / 256, 256>>>(emb, offs, out, sc);
}

// round 17
// speedup vs baseline: 1.9671x; 1.9671x over previous
#include <cuda_runtime.h>
#include <math.h>
#include <stdint.h>

#define N_LEVELS 16
#define N_POINTS 524288
#define HASH_MASK 0x7FFFFu       // hashed level size = 2^19 exactly
#define P1 2654435761u
#define P2 805459861u

#define NBUCK 32768              // 32^3 Morton buckets (~16 pts/bucket)
#define SCAN_BLOCKS 32           // 32 blocks x 1024 elems

// Static scratch (no allocation allowed). __device__ globals are
// zero-initialized at load; the pipeline returns g_hist4 and g_done to zero
// every launch, so graph replays are deterministic with no memset node.
__device__ uint4    g_hist4[NBUCK / 4];   // counts; RETURNED TO ZERO by scanA
__device__ uint4    g_off4[NBUCK / 4];    // exclusive offsets within scan-block
__device__ unsigned g_btot[SCAN_BLOCKS];  // block totals -> exclusive (in scanA)
__device__ unsigned g_done;               // scanA completion ticket (reset each launch)
__device__ unsigned g_rank[N_POINTS];     // within-bucket rank (from histo)
__device__ float4   g_sorted[N_POINTS];   // (x,y,z, bitcast(orig index))

struct Scales { float s[N_LEVELS]; };

// ---------------- sort pipeline ----------------

__device__ __forceinline__ unsigned spread3(unsigned v) {
    v &= 0x3Fu;
    v = (v | (v << 16)) & 0x030000FFu;
    v = (v | (v << 8))  & 0x0300F00Fu;
    v = (v | (v << 4))  & 0x030C30C3u;
    v = (v | (v << 2))  & 0x09249249u;
    return v;
}

__device__ __forceinline__ unsigned bucket_of(float x, float y, float z) {
    unsigned cx = min((unsigned)(x * 32.0f), 31u);
    unsigned cy = min((unsigned)(y * 32.0f), 31u);
    unsigned cz = min((unsigned)(z * 32.0f), 31u);
    return spread3(cx) | (spread3(cy) << 1) | (spread3(cz) << 2);  // 15-bit Morton
}

// histo: count AND capture each point's within-bucket rank (the atomic's
// return value) so the scatter is atomic-free.
__global__ void k_histo(const float* __restrict__ inputs) {
    unsigned i = blockIdx.x * blockDim.x + threadIdx.x;
    float x = inputs[i * 3 + 0];
    float y = inputs[i * 3 + 1];
    float z = inputs[i * 3 + 2];
    unsigned b = bucket_of(x, y, z);
    unsigned* hist = reinterpret_cast<unsigned*>(g_hist4);
    g_rank[i] = atomicAdd(&hist[b], 1u);   // coalesced store
}

// scanA (+fused scanB): 32 blocks x 256 threads; thread t owns ONE uint4
// (warp = 512B contiguous -> fully coalesced). Zeroes g_hist4 for the next
// replay. The LAST block to finish (ticket pattern) exclusive-scans the 32
// block totals in-place and resets the ticket — removes the scanB launch.
__global__ __launch_bounds__(256) void k_scanA() {
    __shared__ unsigned s[256];
    __shared__ unsigned s_last;
    unsigned t = threadIdx.x;
    unsigned gi = blockIdx.x * 256u + t;

    uint4 v = g_hist4[gi];
    unsigned sum = v.x + v.y + v.z + v.w;

    s[t] = sum;
    __syncthreads();
    for (int d = 1; d < 256; d <<= 1) {
        unsigned add = (t >= (unsigned)d) ? s[t - d] : 0u;
        __syncthreads();
        s[t] += add;
        __syncthreads();
    }
    unsigned run = s[t] - sum;     // exclusive prefix of this chunk in block

    uint4 o;
    o.x = run;
    o.y = run + v.x;
    o.z = run + v.x + v.y;
    o.w = run + v.x + v.y + v.z;
    g_off4[gi]  = o;
    g_hist4[gi] = make_uint4(0u, 0u, 0u, 0u);   // ready for next launch

    if (t == 255u) {
        g_btot[blockIdx.x] = s[255];
        __threadfence();
        s_last = (atomicAdd(&g_done, 1u) == SCAN_BLOCKS - 1u) ? 1u : 0u;
    }
    __syncthreads();

    if (s_last && t < 32u) {
        // fused scanB: one warp exclusive-scans the 32 totals via shuffles
        unsigned bv = g_btot[t];
        unsigned xs = bv;
#pragma unroll
        for (int d = 1; d < 32; d <<= 1) {
            unsigned n = __shfl_up_sync(0xFFFFFFFFu, xs, d);
            if (t >= (unsigned)d) xs += n;
        }
        g_btot[t] = xs - bv;            // exclusive
        if (t == 0u) g_done = 0u;       // reset for next graph replay
    }
}

// Scatter: ATOMIC-FREE. slot = captured rank + bucket offset + block offset.
__global__ void k_scatter(const float* __restrict__ inputs) {
    unsigned i = blockIdx.x * blockDim.x + threadIdx.x;
    float x = inputs[i * 3 + 0];
    float y = inputs[i * 3 + 1];
    float z = inputs[i * 3 + 2];
    unsigned b = bucket_of(x, y, z);
    const unsigned* off = reinterpret_cast<const unsigned*>(g_off4);
    unsigned pos = g_rank[i] + __ldg(&off[b]) + __ldg(&g_btot[b >> 10]);
    g_sorted[pos] = make_float4(x, y, z, __uint_as_float(i));
}

// ---------------- main encode ----------------
// (Exact R7/R14 version: ~148us measured, at its L1-wavefront floor with 48
// warps/SM. DO NOT add SMEM, regs, or occupancy constraints — R8/R12/R16
// all proved regressions. One thread per sorted point; a warp = 32
// spatially-clustered points -> lane addresses collapse on coarse/mid levels.)

__global__ __launch_bounds__(256) void hashenc_main(
    const float2* __restrict__ emb,
    const int*    __restrict__ offs,
    float2*       __restrict__ out,
    Scales sc)
{
    const unsigned kRes[5] = {16u, 23u, 31u, 43u, 59u};

    unsigned i = blockIdx.x * 256u + threadIdx.x;
    float4 pt = g_sorted[i];                       // 1 coalesced LDG.128
    float x = pt.x, y = pt.y, z = pt.z;
    unsigned p = __float_as_uint(pt.w);
    float* orow = (float*)out + (size_t)p * 32u;   // 128B row, 16B aligned

#pragma unroll
    for (int h = 0; h < 2; h++) {                  // two halves of 8 levels
        float acc[16];
#pragma unroll
        for (int l8 = 0; l8 < 8; l8++) {
            const int l = h * 8 + l8;
            float scale = sc.s[l];
            // plain fp32 multiply (bit-exact vs jnp inputs*scale)
            float px = x * scale, py = y * scale, pz = z * scale;
            float fx0 = floorf(px), fy0 = floorf(py), fz0 = floorf(pz);
            float fx = px - fx0, fy = py - fy0, fz = pz - fz0;
            unsigned gx = (unsigned)fx0, gy = (unsigned)fy0, gz = (unsigned)fz0;
            unsigned base = (unsigned)__ldg(&offs[l]);

            unsigned idx[8];
            if (l >= 5) {
                // hashed: (cx*1 ^ cy*P1 ^ cz*P2) & (2^19-1)
                unsigned hy0 = gy * P1, hy1 = hy0 + P1;
                unsigned hz0 = gz * P2, hz1 = hz0 + P2;
                unsigned s00 = hy0 ^ hz0, s10 = hy1 ^ hz0;
                unsigned s01 = hy0 ^ hz1, s11 = hy1 ^ hz1;
                unsigned x0 = gx, x1 = gx + 1u;
                idx[0] = (x0 ^ s00) & HASH_MASK;
                idx[1] = (x1 ^ s00) & HASH_MASK;
                idx[2] = (x0 ^ s10) & HASH_MASK;
                idx[3] = (x1 ^ s10) & HASH_MASK;
                idx[4] = (x0 ^ s01) & HASH_MASK;
                idx[5] = (x1 ^ s01) & HASH_MASK;
                idx[6] = (x0 ^ s11) & HASH_MASK;
                idx[7] = (x1 ^ s11) & HASH_MASK;
            } else {
                // dense: row-major within res^3, corners clamped to res-1
                unsigned res = kRes[l];
                unsigned rm1 = res - 1u;
                unsigned rr  = res * res;
                unsigned x0 = min(gx, rm1),       x1 = min(gx + 1u, rm1);
                unsigned y0 = min(gy, rm1) * res, y1 = min(gy + 1u, rm1) * res;
                unsigned z0 = min(gz, rm1) * rr,  z1 = min(gz + 1u, rm1) * rr;
                idx[0] = x0 + y0 + z0;
                idx[1] = x1 + y0 + z0;
                idx[2] = x0 + y1 + z0;
                idx[3] = x1 + y1 + z0;
                idx[4] = x0 + y0 + z1;
                idx[5] = x1 + y0 + z1;
                idx[6] = x0 + y1 + z1;
                idx[7] = x1 + y1 + z1;
            }

            float2 e[8];
#pragma unroll
            for (int c = 0; c < 8; c++)
                e[c] = __ldg(&emb[base + idx[c]]);

            float wx[2] = {1.0f - fx, fx};
            float wy[2] = {1.0f - fy, fy};
            float wz[2] = {1.0f - fz, fz};
            float ox = 0.0f, oy = 0.0f;
#pragma unroll
            for (int c = 0; c < 8; c++) {
                float w = wx[c & 1] * wy[(c >> 1) & 1] * wz[(c >> 2) & 1];
                ox += w * e[c].x;
                oy += w * e[c].y;
            }
            acc[l8 * 2 + 0] = ox;
            acc[l8 * 2 + 1] = oy;
        }
        // Half-row store: 4x STG.128 to this point's contiguous 128B row.
#pragma unroll
        for (int q = 0; q < 4; q++) {
            float4 v = make_float4(acc[q * 4 + 0], acc[q * 4 + 1],
                                   acc[q * 4 + 2], acc[q * 4 + 3]);
            __stcs((float4*)(orow + h * 16) + q, v);
        }
    }
}

// ---------------- launch ----------------

extern "C" void kernel_launch(void* const* d_in, const int* in_sizes, int n_in,
                              void* d_out, int out_size)
{
    const float*  inputs = (const float*)d_in[0];
    const float2* emb    = (const float2*)d_in[1];
    const int*    offs   = (const int*)d_in[2];
    float2*       out    = (float2*)d_out;

    // scale[l] = float32(16 * (2^(7/15))^l), computed in double so the float32
    // cast absorbs any sub-ulp libm difference vs numpy.
    Scales sc;
    double ratio = exp2(7.0 / 15.0);
    for (int l = 0; l < N_LEVELS; l++)
        sc.s[l] = (float)(16.0 * pow(ratio, (double)l));

    k_histo  <<<N_POINTS / 256, 256>>>(inputs);
    k_scanA  <<<SCAN_BLOCKS, 256>>>();      // scanB fused (last-block pattern)
    k_scatter<<<N_POINTS / 256, 256>>>(inputs);
    hashenc_main<<<N_POINTS / 256, 256>>>(emb, offs, out, sc);
}